// round 10
// baseline (speedup 1.0000x reference)
#include <cuda_runtime.h>
#include <cuda_fp16.h>
#include <math.h>
#include <stdint.h>

#define B_  512
#define F_  1280
#define H_  2560
#define KK  8
#define E_  9

#define CH   64
#define NCH  (F_/CH)                // 20
#define SAE  72
#define ROWB (SAE*2)                // 144
#define ABUF_BYTES (128*ROWB)
#define BBUF_BYTES (128*ROWB)
#define STAGE_BYTES (ABUF_BYTES+BBUF_BYTES)  // 36864
#define A_OFF 0
#define B_OFF ABUF_BYTES
#define NSTG 3
#define DYN_BYTES (NSTG*STAGE_BYTES)  // 110592 -> 2 CTAs/SM
#define HTS 130
#define EP_W2_OFF  66560
#define EP_B1_OFF  70656

#define NCONV 3600      // (e, kc, nb) tiles
#define NGEMM 720       // (e, nb, mb)
#define NTASK (NCONV+NGEMM)
#define NGRP  180       // (e, nb) groups

__device__ __half gW[(size_t)E_*H_*F_];       // W1^T fp16 [e][n][k]
__device__ __half gX[(size_t)B_*F_];          // x fp16 [b][k]
__device__ float gPart[(size_t)E_*20*B_*KK];
__device__ unsigned int gQHead;
__device__ int gDone[NGRP];

__device__ __forceinline__ uint32_t smem_u32(const void* p){
    uint32_t a; asm("{ .reg .u64 t; cvta.to.shared.u64 t, %1; cvt.u32.u64 %0, t; }":"=r"(a):"l"(p)); return a;
}
#define CP16(dst,src) asm volatile("cp.async.cg.shared.global [%0], [%1], 16;"::"r"(dst),"l"(src):"memory")
#define LDM4(r,addr) asm volatile("ldmatrix.sync.aligned.m8n8.x4.shared.b16 {%0,%1,%2,%3}, [%4];" \
    : "=r"((r)[0]),"=r"((r)[1]),"=r"((r)[2]),"=r"((r)[3]) : "r"(addr))
__device__ __forceinline__ void mma_f16(float* c, const uint32_t* a, const uint32_t* b){
    asm volatile("mma.sync.aligned.m16n8k16.row.col.f32.f16.f16.f32 "
        "{%0,%1,%2,%3},{%4,%5,%6,%7},{%8,%9},{%0,%1,%2,%3};"
        : "+f"(c[0]),"+f"(c[1]),"+f"(c[2]),"+f"(c[3])
        : "r"(a[0]),"r"(a[1]),"r"(a[2]),"r"(a[3]),"r"(b[0]),"r"(b[1]));
}
__device__ __forceinline__ uint32_t pack2(float a, float b){
    __half2 h = __floats2half2_rn(a, b);
    return *reinterpret_cast<uint32_t*>(&h);
}

__global__ void reset_kernel(){
    int i = threadIdx.x;
    if(i==0) gQHead = 0u;
    if(i < NGRP) gDone[i] = 0;
}

// ---- x -> fp16. 163840 float4s.
__global__ __launch_bounds__(256) void conv_x_kernel(const float* __restrict__ x){
    int i = blockIdx.x*256 + threadIdx.x;
    float4 v = ((const float4*)x)[i];
    uint2 o;
    o.x = pack2(v.x, v.y);
    o.y = pack2(v.z, v.w);
    ((uint2*)gX)[i] = o;
}

// queue order: conv(e0),conv(e1), then for blk=0..6: [conv(e=blk+2) 400 | gemm(e=blk) 80], then gemm e7,e8
__device__ __forceinline__ void decode(unsigned idx, int& isConv, int& t){
    if(idx < 800u){ isConv = 1; t = (int)idx; return; }
    unsigned r = idx - 800u;
    unsigned blk = r / 480u;
    unsigned off = r % 480u;
    if(blk < 7u){
        if(off < 400u){ isConv = 1; t = (int)((blk+2u)*400u + off); }
        else          { isConv = 0; t = (int)(blk*80u + (off-400u)); }
    } else {
        isConv = 0; t = (int)(560u + (r - 3360u));
    }
}

// ---- persistent fused conversion + GEMM kernel
__global__ __launch_bounds__(256,2) void fused_kernel(const float* __restrict__ W1,
                                                      const float* __restrict__ W2,
                                                      const float* __restrict__ b1){
    extern __shared__ char dyn[];
    __shared__ unsigned sTask;
    const int tid = threadIdx.x, lane = tid & 31, wid = tid >> 5;
    const uint32_t dynU = smem_u32(dyn);

    for(;;){
        if(tid == 0) sTask = atomicAdd(&gQHead, 1u);
        __syncthreads();
        unsigned idx = sTask;
        __syncthreads();              // all threads consumed sTask before next overwrite
        if(idx >= NTASK) break;
        int isConv, t;
        decode(idx, isConv, t);

        if(isConv){
            // ---- conversion tile: t = e*400 + kc*20 + nb ; 64k x 128n
            float (*s)[129] = (float(*)[129])dyn;
            int nb = t % 20, kc = (t/20) % 20, e = t/400;
            const float* src = W1 + ((size_t)e*F_ + (size_t)kc*64)*H_ + (size_t)nb*128;
            for(int i=tid; i<64*128; i+=256){
                int kk = i>>7, r = i&127;
                s[kk][r] = src[(size_t)kk*H_ + r];
            }
            __syncthreads();
            int kg = tid & 7, rbase = tid >> 3;
#pragma unroll
            for(int u=0; u<4; u++){
                int row = u*32 + rbase;
                uint4 o;
                o.x = pack2(s[kg*8+0][row], s[kg*8+1][row]);
                o.y = pack2(s[kg*8+2][row], s[kg*8+3][row]);
                o.z = pack2(s[kg*8+4][row], s[kg*8+5][row]);
                o.w = pack2(s[kg*8+6][row], s[kg*8+7][row]);
                size_t off = (size_t)e*H_*F_ + (size_t)(nb*128+row)*F_ + kc*64 + kg*8;
                *(uint4*)(gW+off) = o;
            }
            __threadfence();
            __syncthreads();
            if(tid == 0) atomicAdd(&gDone[e*20+nb], 1);
            __syncthreads();
        } else {
            // ---- gemm tile: t = e*80 + nb*4 + mb
            const int e = t/80, nb = (t%80)>>2, mb = t&3;
            const int m0 = mb*128, n0 = nb*128;
            // wait for this (e,nb) group's 20 conversion tiles
            if(tid == 0){
                while(atomicAdd(&gDone[e*20+nb], 0) < 20) __nanosleep(64);
            }
            __syncthreads();
            __threadfence();

            const int warp_m = wid & 3, warp_n = wid >> 2;
            const int seg = tid & 7;
            const __half* gA = gX + (size_t)m0*F_;
            const __half* gB = gW + ((size_t)e*H_ + n0)*F_;
            const int r0 = tid>>3, r1 = (tid+256)>>3, r2 = (tid+512)>>3, r3 = (tid+768)>>3;

            uint32_t stB[NSTG];
#pragma unroll
            for(int s=0;s<NSTG;s++) stB[s] = dynU + s*STAGE_BYTES;

#define ISSUE(c) do{ \
    uint32_t st_ = stB[(c)%NSTG]; int ko_ = (c)*CH + seg*8; \
    CP16(st_+A_OFF + r0*ROWB + seg*16, gA + (size_t)r0*F_ + ko_); \
    CP16(st_+A_OFF + r1*ROWB + seg*16, gA + (size_t)r1*F_ + ko_); \
    CP16(st_+A_OFF + r2*ROWB + seg*16, gA + (size_t)r2*F_ + ko_); \
    CP16(st_+A_OFF + r3*ROWB + seg*16, gA + (size_t)r3*F_ + ko_); \
    CP16(st_+B_OFF + r0*ROWB + seg*16, gB + (size_t)r0*F_ + ko_); \
    CP16(st_+B_OFF + r1*ROWB + seg*16, gB + (size_t)r1*F_ + ko_); \
    CP16(st_+B_OFF + r2*ROWB + seg*16, gB + (size_t)r2*F_ + ko_); \
    CP16(st_+B_OFF + r3*ROWB + seg*16, gB + (size_t)r3*F_ + ko_); \
    asm volatile("cp.async.commit_group;":::"memory"); }while(0)

            const uint32_t aBase = A_OFF + (uint32_t)(warp_m*32 + (lane & 15))*ROWB + ((lane>>4)<<3)*2;
            const uint32_t bBase = B_OFF + (uint32_t)(warp_n*64 + ((lane>>4)&1)*8 + (lane&7))*ROWB + (((lane>>3)&1)<<3)*2;

            float acc[2][8][4];
#pragma unroll
            for(int a=0;a<2;a++)
#pragma unroll
            for(int b=0;b<8;b++)
#pragma unroll
            for(int d=0;d<4;d++) acc[a][b][d]=0.f;

            ISSUE(0); ISSUE(1);
            for(int c=0;c<NCH;c++){
                asm volatile("cp.async.wait_group 1;":::"memory");
                __syncthreads();
                if(c+2<NCH) ISSUE(c+2);
                const uint32_t st = stB[c%NSTG];
                const uint32_t ab = st + aBase, bb = st + bBase;
#pragma unroll
                for(int ks=0; ks<4; ks++){
                    uint32_t ah[2][4];
#pragma unroll
                    for(int mi=0; mi<2; mi++)
                        LDM4(ah[mi], ab + mi*16*ROWB + ks*32);
#pragma unroll
                    for(int nj=0; nj<4; nj++){
                        uint32_t bt[4];
                        LDM4(bt, bb + nj*16*ROWB + ks*32);
#pragma unroll
                        for(int mi=0; mi<2; mi++){
                            mma_f16(acc[mi][nj*2+0], ah[mi], &bt[0]);
                            mma_f16(acc[mi][nj*2+1], ah[mi], &bt[2]);
                        }
                    }
                }
            }
#undef ISSUE
            // drain remaining cp.async group (last ISSUE already consumed; wait 0 for safety)
            asm volatile("cp.async.wait_group 0;":::"memory");
            __syncthreads();

            float* w2s   = (float*)(dyn + EP_W2_OFF);
            float* biass = (float*)(dyn + EP_B1_OFF);
            ((float4*)w2s)[tid] = ((const float4*)(W2 + ((size_t)e*H_ + n0)*KK))[tid];
            if(tid < 32) ((float4*)biass)[tid] = ((const float4*)(b1 + (size_t)e*H_ + n0))[tid];
            __syncthreads();

            float* ht = (float*)dyn;
            const int g = lane >> 2, tg2 = (lane & 3)*2;
#pragma unroll
            for(int mi=0; mi<2; mi++){
                int rr = warp_m*32 + mi*16 + g;
#pragma unroll
                for(int ni=0; ni<8; ni++){
                    int c0 = warp_n*64 + ni*8 + tg2;
                    float2 v0, v1;
                    v0.x = fmaxf(acc[mi][ni][0] + biass[c0],   0.f);
                    v0.y = fmaxf(acc[mi][ni][1] + biass[c0+1], 0.f);
                    v1.x = fmaxf(acc[mi][ni][2] + biass[c0],   0.f);
                    v1.y = fmaxf(acc[mi][ni][3] + biass[c0+1], 0.f);
                    *(float2*)&ht[(size_t)rr*HTS + c0]     = v0;
                    *(float2*)&ht[(size_t)(rr+8)*HTS + c0] = v1;
                }
            }
            __syncthreads();
            {
                const int row = tid >> 1, q = tid & 1;
                const float* hp = &ht[(size_t)row*HTS + q*64];
                const float* wp = &w2s[q*64*8];
                float pl[8];
#pragma unroll
                for(int k=0;k<8;k++) pl[k]=0.f;
#pragma unroll
                for(int cc=0; cc<64; cc++){
                    int cr = (cc + q*9) & 63;
                    float h = hp[cr];
                    const float4* w4 = (const float4*)&wp[cr*8];
                    float4 wa = w4[0], wb = w4[1];
                    pl[0]=fmaf(h,wa.x,pl[0]); pl[1]=fmaf(h,wa.y,pl[1]);
                    pl[2]=fmaf(h,wa.z,pl[2]); pl[3]=fmaf(h,wa.w,pl[3]);
                    pl[4]=fmaf(h,wb.x,pl[4]); pl[5]=fmaf(h,wb.y,pl[5]);
                    pl[6]=fmaf(h,wb.z,pl[6]); pl[7]=fmaf(h,wb.w,pl[7]);
                }
#pragma unroll
                for(int k=0;k<8;k++) pl[k] += __shfl_xor_sync(0xFFFFFFFFu, pl[k], 1);
                float* dst = gPart + (((size_t)e*20 + nb)*B_ + (m0+row))*KK + q*4;
                *(float4*)dst = make_float4(pl[q*4], pl[q*4+1], pl[q*4+2], pl[q*4+3]);
            }
            __syncthreads();
        }
    }
}

// ---- tail: sum 20 partials per (e,k), +b2, softmax, path products
__global__ __launch_bounds__(256) void tail_kernel(const float* __restrict__ b2,
                                                   float* __restrict__ out){
    const int b = blockIdx.x, tid = threadIdx.x;
    __shared__ float part[180][8];
    __shared__ float logits_s[9][8];
    __shared__ float probs_s[9][8];
    for(int t=tid; t<180; t+=256){
        const float4* src = (const float4*)(gPart + ((size_t)t*B_ + b)*KK);
        *(float4*)&part[t][0] = src[0];
        *(float4*)&part[t][4] = src[1];
    }
    __syncthreads();
    if(tid < 72){
        int e = tid>>3, k = tid&7;
        float s = 0.f;
#pragma unroll
        for(int j=0;j<20;j++) s += part[e*20+j][k];
        float lv = s + b2[tid];
        logits_s[e][k] = lv;
        out[(size_t)B_*73 + ((size_t)e*B_ + b)*KK + k] = lv;
    }
    __syncthreads();
    if(tid < 9){
        float m = -INFINITY;
#pragma unroll
        for(int k=0;k<8;k++) m = fmaxf(m, logits_s[tid][k]);
        float ex[8], s = 0.f;
#pragma unroll
        for(int k=0;k<8;k++){ ex[k] = expf(logits_s[tid][k]-m); s += ex[k]; }
        float inv = 1.f/s;
#pragma unroll
        for(int k=0;k<8;k++) probs_s[tid][k] = ex[k]*inv;
    }
    __syncthreads();
    if(tid < 73){
        float v;
        if(tid==0) v = 1.f;
        else if(tid<9) v = probs_s[0][tid-1];
        else { int t = tid-9; v = probs_s[0][t>>3]*probs_s[1+(t>>3)][t&7]; }
        out[(size_t)b*73 + tid] = v;
    }
}

extern "C" void kernel_launch(void* const* d_in, const int* in_sizes, int n_in,
                              void* d_out, int out_size){
    const float* x  = (const float*)d_in[0];
    const float* W1 = (const float*)d_in[1];
    const float* b1 = (const float*)d_in[2];
    const float* W2 = (const float*)d_in[3];
    const float* b2 = (const float*)d_in[4];
    float* out = (float*)d_out;

    cudaFuncSetAttribute(fused_kernel, cudaFuncAttributeMaxDynamicSharedMemorySize, DYN_BYTES);

    reset_kernel<<<1, 256>>>();
    conv_x_kernel<<<640, 256>>>(x);
    fused_kernel<<<296, 256, DYN_BYTES>>>(W1, W2, b1);
    tail_kernel<<<B_, 256>>>(b2, out);
}

// round 11
// speedup vs baseline: 1.1839x; 1.1839x over previous
#include <cuda_runtime.h>
#include <cuda_fp16.h>
#include <math.h>
#include <stdint.h>

#define B_  512
#define F_  1280
#define H_  2560
#define KK  8
#define E_  9

#define CH    32                    // k per chunk
#define NCH   (F_/CH)               // 40
#define ROWB  80                    // fp16 buf row stride bytes (32 fp16 + pad) — R4-proven
#define ABUF  (128*ROWB)            // 10240
#define BF32ROWB 528                // fp32 staging row stride bytes (128 fl + 4 pad)
#define BF32BUF  (CH*BF32ROWB)      // 16896
#define STAGE (ABUF+BF32BUF)        // 27136
#define NSTG  3
#define BH16_OFF (NSTG*STAGE)       // 81408
#define DYN_BYTES (BH16_OFF+ABUF)   // 91648 -> 2 CTAs/SM
#define HTS 130
#define EP_W2_OFF  66560
#define EP_B1_OFF  70656

__device__ __half gX[(size_t)B_*F_];          // x fp16 [b][k]
__device__ float gPart[(size_t)E_*20*B_*KK];  // [e][nb][b][8]

__device__ __forceinline__ uint32_t smem_u32(const void* p){
    uint32_t a; asm("{ .reg .u64 t; cvta.to.shared.u64 t, %1; cvt.u32.u64 %0, t; }":"=r"(a):"l"(p)); return a;
}
#define CP16(dst,src) asm volatile("cp.async.cg.shared.global [%0], [%1], 16;"::"r"(dst),"l"(src):"memory")
#define LDM4(r,addr) asm volatile("ldmatrix.sync.aligned.m8n8.x4.shared.b16 {%0,%1,%2,%3}, [%4];" \
    : "=r"((r)[0]),"=r"((r)[1]),"=r"((r)[2]),"=r"((r)[3]) : "r"(addr))
__device__ __forceinline__ void mma_f16(float* c, const uint32_t* a, const uint32_t* b){
    asm volatile("mma.sync.aligned.m16n8k16.row.col.f32.f16.f16.f32 "
        "{%0,%1,%2,%3},{%4,%5,%6,%7},{%8,%9},{%0,%1,%2,%3};"
        : "+f"(c[0]),"+f"(c[1]),"+f"(c[2]),"+f"(c[3])
        : "r"(a[0]),"r"(a[1]),"r"(a[2]),"r"(a[3]),"r"(b[0]),"r"(b[1]));
}
__device__ __forceinline__ uint32_t pack2(float a, float b){
    __half2 h = __floats2half2_rn(a, b);
    return *reinterpret_cast<uint32_t*>(&h);
}

// ---- x -> fp16. 163840 float4s.
__global__ __launch_bounds__(256) void conv_x_kernel(const float* __restrict__ x){
    int i = blockIdx.x*256 + threadIdx.x;
    float4 v = ((const float4*)x)[i];
    uint2 o;
    o.x = pack2(v.x, v.y);
    o.y = pack2(v.z, v.w);
    ((uint2*)gX)[i] = o;
}

// ---- GEMM1 with in-kernel W1 transpose+convert, fused bias/ReLU + GEMM2 partials.
// grid (4 mb, 20 nb, 9 e) = 720 CTAs, 256 threads, 2 CTAs/SM.
// CTA tile 128x128; warp grid 4(m) x 2(n); warp tile 32x64; CH=32.
__global__ __launch_bounds__(256,2) void gemm_kernel(const float* __restrict__ W1,
                                                     const float* __restrict__ W2,
                                                     const float* __restrict__ b1){
    extern __shared__ char dyn[];
    const int tid = threadIdx.x, lane = tid & 31, wid = tid >> 5;
    const int warp_m = wid & 3, warp_n = wid >> 2;
    const int m0 = blockIdx.x*128, n0 = blockIdx.y*128, e = blockIdx.z;
    const uint32_t dynU = smem_u32(dyn);
    const uint32_t bh16 = dynU + BH16_OFF;

    // A cp.async: 128 rows x 4 segs of 16B = 512 tasks, 2/thread
    const int aseg = tid & 3;
    const int arw0 = tid >> 2, arw1 = (tid+256) >> 2;
    const __half* gA = gX + (size_t)m0*F_;
    // B cp.async (fp32, native [k][n]): 32 k-rows x 32 segs of 16B = 1024 tasks, 4/thread
    const int bseg = tid & 31;
    const int bk0 = tid>>5, bk1 = (tid+256)>>5, bk2 = (tid+512)>>5, bk3 = (tid+768)>>5;
    const float* gBW = W1 + (size_t)e*F_*H_ + n0;   // + (c*CH+kk)*H_ + seg*4

    uint32_t stA[NSTG], stF[NSTG];
#pragma unroll
    for(int s=0;s<NSTG;s++){ stA[s] = dynU + s*STAGE; stF[s] = stA[s] + ABUF; }

#define ISSUE(c) do{ \
    uint32_t sa_ = stA[(c)%NSTG], sf_ = stF[(c)%NSTG]; int ko_ = (c)*CH; \
    CP16(sa_ + arw0*ROWB + aseg*16, gA + (size_t)arw0*F_ + ko_ + aseg*8); \
    CP16(sa_ + arw1*ROWB + aseg*16, gA + (size_t)arw1*F_ + ko_ + aseg*8); \
    CP16(sf_ + bk0*BF32ROWB + bseg*16, gBW + (size_t)(ko_+bk0)*H_ + bseg*4); \
    CP16(sf_ + bk1*BF32ROWB + bseg*16, gBW + (size_t)(ko_+bk1)*H_ + bseg*4); \
    CP16(sf_ + bk2*BF32ROWB + bseg*16, gBW + (size_t)(ko_+bk2)*H_ + bseg*4); \
    CP16(sf_ + bk3*BF32ROWB + bseg*16, gBW + (size_t)(ko_+bk3)*H_ + bseg*4); \
    asm volatile("cp.async.commit_group;":::"memory"); }while(0)

    // ldmatrix bases
    const uint32_t aBase = (uint32_t)(warp_m*32 + (lane & 15))*ROWB + ((lane>>4)<<3)*2;
    const uint32_t bBase = bh16 + (uint32_t)(warp_n*64 + ((lane>>4)&1)*8 + (lane&7))*ROWB + (((lane>>3)&1)<<3)*2;
    // convert mapping: n = tid>>1 (0..127), kg = tid&1 (k halves)
    const int cvN = tid >> 1, cvKg = tid & 1;

    float acc[2][8][4];
#pragma unroll
    for(int a=0;a<2;a++)
#pragma unroll
    for(int b=0;b<8;b++)
#pragma unroll
    for(int d=0;d<4;d++) acc[a][b][d]=0.f;

    ISSUE(0); ISSUE(1);
    for(int c=0;c<NCH;c++){
        asm volatile("cp.async.wait_group 1;":::"memory");
        __syncthreads();
        if(c+2<NCH) ISSUE(c+2);
        // transpose+convert Bf32[c] -> Bh16
        {
            const uint32_t sf = stF[c%NSTG];
            float f[16];
#pragma unroll
            for(int j=0;j<16;j++){
                uint32_t ad = sf + (uint32_t)(cvKg*16 + j)*BF32ROWB + cvN*4;
                asm volatile("ld.shared.f32 %0, [%1];" : "=f"(f[j]) : "r"(ad));
            }
            uint32_t h[8];
#pragma unroll
            for(int j=0;j<8;j++) h[j] = pack2(f[2*j], f[2*j+1]);
            uint32_t wd = bh16 + (uint32_t)cvN*ROWB + cvKg*32;
            asm volatile("st.shared.v4.b32 [%0], {%1,%2,%3,%4};"
                         :: "r"(wd), "r"(h[0]),"r"(h[1]),"r"(h[2]),"r"(h[3]) : "memory");
            asm volatile("st.shared.v4.b32 [%0], {%1,%2,%3,%4};"
                         :: "r"(wd+16), "r"(h[4]),"r"(h[5]),"r"(h[6]),"r"(h[7]) : "memory");
        }
        __syncthreads();
        const uint32_t ab = stA[c%NSTG] + aBase;
#pragma unroll
        for(int ks=0; ks<2; ks++){
            uint32_t ah[2][4];
#pragma unroll
            for(int mi=0; mi<2; mi++)
                LDM4(ah[mi], ab + mi*16*ROWB + ks*32);
#pragma unroll
            for(int nj=0; nj<4; nj++){
                uint32_t bt[4];
                LDM4(bt, bBase + nj*16*ROWB + ks*32);
#pragma unroll
                for(int mi=0; mi<2; mi++){
                    mma_f16(acc[mi][nj*2+0], ah[mi], &bt[0]);
                    mma_f16(acc[mi][nj*2+1], ah[mi], &bt[2]);
                }
            }
        }
    }
#undef ISSUE
    asm volatile("cp.async.wait_group 0;":::"memory");
    __syncthreads();

    // W2 tile + bias into dyn smem (past htile region)
    float* w2s   = (float*)(dyn + EP_W2_OFF);
    float* biass = (float*)(dyn + EP_B1_OFF);
    ((float4*)w2s)[tid] = ((const float4*)(W2 + ((size_t)e*H_ + n0)*KK))[tid];
    if(tid < 32) ((float4*)biass)[tid] = ((const float4*)(b1 + (size_t)e*H_ + n0))[tid];
    __syncthreads();

    // epilogue: bias + ReLU -> htile [128][HTS]
    float* ht = (float*)dyn;
    const int g = lane >> 2, tg2 = (lane & 3)*2;
#pragma unroll
    for(int mi=0; mi<2; mi++){
        int rr = warp_m*32 + mi*16 + g;
#pragma unroll
        for(int ni=0; ni<8; ni++){
            int c0 = warp_n*64 + ni*8 + tg2;
            float2 v0, v1;
            v0.x = fmaxf(acc[mi][ni][0] + biass[c0],   0.f);
            v0.y = fmaxf(acc[mi][ni][1] + biass[c0+1], 0.f);
            v1.x = fmaxf(acc[mi][ni][2] + biass[c0],   0.f);
            v1.y = fmaxf(acc[mi][ni][3] + biass[c0+1], 0.f);
            *(float2*)&ht[(size_t)rr*HTS + c0]     = v0;
            *(float2*)&ht[(size_t)(rr+8)*HTS + c0] = v1;
        }
    }
    __syncthreads();

    // GEMM2 partials: 256 threads -> 128 rows x 2 halves of 64 cols
    {
        const int row = tid >> 1, q = tid & 1;
        const float* hp = &ht[(size_t)row*HTS + q*64];
        const float* wp = &w2s[q*64*8];
        float pl[8];
#pragma unroll
        for(int k=0;k<8;k++) pl[k]=0.f;
#pragma unroll
        for(int cc=0; cc<64; cc++){
            int cr = (cc + q*9) & 63;
            float h = hp[cr];
            const float4* w4 = (const float4*)&wp[cr*8];
            float4 wa = w4[0], wb = w4[1];
            pl[0]=fmaf(h,wa.x,pl[0]); pl[1]=fmaf(h,wa.y,pl[1]);
            pl[2]=fmaf(h,wa.z,pl[2]); pl[3]=fmaf(h,wa.w,pl[3]);
            pl[4]=fmaf(h,wb.x,pl[4]); pl[5]=fmaf(h,wb.y,pl[5]);
            pl[6]=fmaf(h,wb.z,pl[6]); pl[7]=fmaf(h,wb.w,pl[7]);
        }
#pragma unroll
        for(int k=0;k<8;k++) pl[k] += __shfl_xor_sync(0xFFFFFFFFu, pl[k], 1);
        float* dst = gPart + (((size_t)e*20 + blockIdx.y)*B_ + (m0+row))*KK + q*4;
        *(float4*)dst = make_float4(pl[q*4], pl[q*4+1], pl[q*4+2], pl[q*4+3]);
    }
}

// ---- tail: sum 20 partials per (e,k), +b2, softmax, path products
__global__ __launch_bounds__(256) void tail_kernel(const float* __restrict__ b2,
                                                   float* __restrict__ out){
    const int b = blockIdx.x, tid = threadIdx.x;
    __shared__ float part[180][8];
    __shared__ float logits_s[9][8];
    __shared__ float probs_s[9][8];
    for(int t=tid; t<180; t+=256){
        const float4* src = (const float4*)(gPart + ((size_t)t*B_ + b)*KK);
        *(float4*)&part[t][0] = src[0];
        *(float4*)&part[t][4] = src[1];
    }
    __syncthreads();
    if(tid < 72){
        int e = tid>>3, k = tid&7;
        float s = 0.f;
#pragma unroll
        for(int j=0;j<20;j++) s += part[e*20+j][k];
        float lv = s + b2[tid];
        logits_s[e][k] = lv;
        out[(size_t)B_*73 + ((size_t)e*B_ + b)*KK + k] = lv;
    }
    __syncthreads();
    if(tid < 9){
        float m = -INFINITY;
#pragma unroll
        for(int k=0;k<8;k++) m = fmaxf(m, logits_s[tid][k]);
        float ex[8], s = 0.f;
#pragma unroll
        for(int k=0;k<8;k++){ ex[k] = expf(logits_s[tid][k]-m); s += ex[k]; }
        float inv = 1.f/s;
#pragma unroll
        for(int k=0;k<8;k++) probs_s[tid][k] = ex[k]*inv;
    }
    __syncthreads();
    if(tid < 73){
        float v;
        if(tid==0) v = 1.f;
        else if(tid<9) v = probs_s[0][tid-1];
        else { int t = tid-9; v = probs_s[0][t>>3]*probs_s[1+(t>>3)][t&7]; }
        out[(size_t)b*73 + tid] = v;
    }
}

extern "C" void kernel_launch(void* const* d_in, const int* in_sizes, int n_in,
                              void* d_out, int out_size){
    const float* x  = (const float*)d_in[0];
    const float* W1 = (const float*)d_in[1];
    const float* b1 = (const float*)d_in[2];
    const float* W2 = (const float*)d_in[3];
    const float* b2 = (const float*)d_in[4];
    float* out = (float*)d_out;

    cudaFuncSetAttribute(gemm_kernel, cudaFuncAttributeMaxDynamicSharedMemorySize, DYN_BYTES);

    conv_x_kernel<<<640, 256>>>(x);
    dim3 grid(4, 20, 9);
    gemm_kernel<<<grid, 256, DYN_BYTES>>>(W1, W2, b1);
    tail_kernel<<<B_, 256>>>(b2, out);
}

// round 12
// speedup vs baseline: 1.3198x; 1.1147x over previous
#include <cuda_runtime.h>
#include <cuda_fp16.h>
#include <math.h>
#include <stdint.h>

#define B_  512
#define F_  1280
#define H_  2560
#define KK  8
#define E_  9

#define BN   160
#define NB   (H_/BN)                // 16
#define CH   32                     // k per chunk
#define NCH  (F_/CH)                // 40
#define ROWB 80                     // row stride bytes (32 fp16 + 16B pad) — R4-proven
#define ABUF (128*ROWB)             // 10240
#define BBUF (BN*ROWB)              // 12800
#define STAGE (ABUF+BBUF)           // 23040
#define A_OFF 0
#define B_OFF ABUF
#define NSTG 4
#define DYN_BYTES (NSTG*STAGE)      // 92160 -> 2 CTAs/SM
#define HTS 162                     // htile row stride (floats), even
#define EP_W2_OFF  82944            // 128*162*4
#define EP_B1_OFF  (EP_W2_OFF+BN*8*4)  // +5120 = 88064 ; bias 640 -> 88704 <= 92160

__device__ __half gW[(size_t)E_*H_*F_];       // W1^T fp16 [e][n][k]
__device__ __half gX[(size_t)B_*F_];          // x fp16 [b][k]
__device__ float gPart[(size_t)E_*NB*B_*KK];  // [e][nb][b][8]

__device__ __forceinline__ uint32_t smem_u32(const void* p){
    uint32_t a; asm("{ .reg .u64 t; cvta.to.shared.u64 t, %1; cvt.u32.u64 %0, t; }":"=r"(a):"l"(p)); return a;
}
#define CP16(dst,src) asm volatile("cp.async.cg.shared.global [%0], [%1], 16;"::"r"(dst),"l"(src):"memory")
#define LDM4(r,addr) asm volatile("ldmatrix.sync.aligned.m8n8.x4.shared.b16 {%0,%1,%2,%3}, [%4];" \
    : "=r"((r)[0]),"=r"((r)[1]),"=r"((r)[2]),"=r"((r)[3]) : "r"(addr))
__device__ __forceinline__ void mma_f16(float* c, const uint32_t* a, const uint32_t* b){
    asm volatile("mma.sync.aligned.m16n8k16.row.col.f32.f16.f16.f32 "
        "{%0,%1,%2,%3},{%4,%5,%6,%7},{%8,%9},{%0,%1,%2,%3};"
        : "+f"(c[0]),"+f"(c[1]),"+f"(c[2]),"+f"(c[3])
        : "r"(a[0]),"r"(a[1]),"r"(a[2]),"r"(a[3]),"r"(b[0]),"r"(b[1]));
}
__device__ __forceinline__ uint32_t pack2(float a, float b){
    __half2 h = __floats2half2_rn(a, b);
    return *reinterpret_cast<uint32_t*>(&h);
}

// ---- x -> fp16. 163840 float4s.
__global__ __launch_bounds__(256) void conv_x_kernel(const float* __restrict__ x){
    int i = blockIdx.x*256 + threadIdx.x;
    float4 v = ((const float4*)x)[i];
    uint2 o;
    o.x = pack2(v.x, v.y);
    o.y = pack2(v.z, v.w);
    ((uint2*)gX)[i] = o;
}

// ---- W1 [e][k][n] -> W1^T fp16 [e][n][k]. grid 3600 (tiles of 64k x 128n).
__global__ __launch_bounds__(256) void conv_w1_kernel(const float* __restrict__ W1){
    __shared__ float s[64][129];
    int tile = blockIdx.x;
    int nb = tile % 20, kc = (tile/20) % 20, e = tile/400;
    const float* src = W1 + ((size_t)e*F_ + (size_t)kc*64)*H_ + (size_t)nb*128;
    for(int i=threadIdx.x; i<64*128; i+=256){
        int kk = i>>7, r = i&127;
        s[kk][r] = src[(size_t)kk*H_ + r];
    }
    __syncthreads();
    int kg = threadIdx.x & 7;
    int rbase = threadIdx.x >> 3;
#pragma unroll
    for(int u=0; u<4; u++){
        int row = u*32 + rbase;
        uint4 o;
        o.x = pack2(s[kg*8+0][row], s[kg*8+1][row]);
        o.y = pack2(s[kg*8+2][row], s[kg*8+3][row]);
        o.z = pack2(s[kg*8+4][row], s[kg*8+5][row]);
        o.w = pack2(s[kg*8+6][row], s[kg*8+7][row]);
        size_t off = (size_t)e*H_*F_ + (size_t)(nb*128+row)*F_ + kc*64 + kg*8;
        *(uint4*)(gW+off) = o;
    }
}

// ---- GEMM1 + fused bias/ReLU + GEMM2 partials.
// grid (4 mb, 16 nb, 9 e) = 576 CTAs, 256 threads, 2 CTAs/SM -> 1.95 waves.
// CTA tile 128x160; warp grid 4(m) x 2(n); warp tile 32x80; CH=32, 4-stage.
__global__ __launch_bounds__(256,2) void gemm_kernel(const float* __restrict__ W2,
                                                     const float* __restrict__ b1){
    extern __shared__ char dyn[];
    const int tid = threadIdx.x, lane = tid & 31, wid = tid >> 5;
    const int warp_m = wid & 3, warp_n = wid >> 2;
    const int m0 = blockIdx.x*128, n0 = blockIdx.y*BN, e = blockIdx.z;
    const uint32_t dynU = smem_u32(dyn);

    // cp.async mapping (per chunk): A = 128 rows x 4 segs = 512 tasks (2/thread);
    //                               B = 160 rows x 4 segs = 640 tasks (2/thread + 128 guarded)
    const int aseg = tid & 3;
    const int ar0 = tid >> 2, ar1 = (tid+256) >> 2;
    const int br0 = tid >> 2, br1 = (tid+256) >> 2, br2 = (tid+512) >> 2;  // br2 valid if tid<128
    const __half* gA = gX + (size_t)m0*F_;
    const __half* gB = gW + ((size_t)e*H_ + n0)*F_;

    uint32_t stB[NSTG];
#pragma unroll
    for(int s=0;s<NSTG;s++) stB[s] = dynU + s*STAGE;

#define ISSUE(c) do{ \
    uint32_t st_ = stB[(c)%NSTG]; int ko_ = (c)*CH + aseg*8; \
    CP16(st_+A_OFF + ar0*ROWB + aseg*16, gA + (size_t)ar0*F_ + ko_); \
    CP16(st_+A_OFF + ar1*ROWB + aseg*16, gA + (size_t)ar1*F_ + ko_); \
    CP16(st_+B_OFF + br0*ROWB + aseg*16, gB + (size_t)br0*F_ + ko_); \
    CP16(st_+B_OFF + br1*ROWB + aseg*16, gB + (size_t)br1*F_ + ko_); \
    if(tid < 128) CP16(st_+B_OFF + br2*ROWB + aseg*16, gB + (size_t)br2*F_ + ko_); \
    asm volatile("cp.async.commit_group;":::"memory"); }while(0)

    const uint32_t aBase = A_OFF + (uint32_t)(warp_m*32 + (lane & 15))*ROWB + ((lane>>4)<<3)*2;
    const uint32_t bBase = B_OFF + (uint32_t)(warp_n*80 + ((lane>>4)&1)*8 + (lane&7))*ROWB + (((lane>>3)&1)<<3)*2;

    float acc[2][10][4];
#pragma unroll
    for(int a=0;a<2;a++)
#pragma unroll
    for(int b=0;b<10;b++)
#pragma unroll
    for(int d=0;d<4;d++) acc[a][b][d]=0.f;

    ISSUE(0); ISSUE(1); ISSUE(2);
    for(int c=0;c<NCH;c++){
        asm volatile("cp.async.wait_group 2;":::"memory");
        __syncthreads();
        if(c+3<NCH) ISSUE(c+3);
        const uint32_t st = stB[c%NSTG];
        const uint32_t ab = st + aBase, bb = st + bBase;
#pragma unroll
        for(int ks=0; ks<2; ks++){
            uint32_t ah[2][4];
#pragma unroll
            for(int mi=0; mi<2; mi++)
                LDM4(ah[mi], ab + mi*16*ROWB + ks*32);
#pragma unroll
            for(int nj=0; nj<5; nj++){
                uint32_t bt[4];
                LDM4(bt, bb + nj*16*ROWB + ks*32);
#pragma unroll
                for(int mi=0; mi<2; mi++){
                    mma_f16(acc[mi][nj*2+0], ah[mi], &bt[0]);
                    mma_f16(acc[mi][nj*2+1], ah[mi], &bt[2]);
                }
            }
        }
    }
#undef ISSUE
    asm volatile("cp.async.wait_group 0;":::"memory");
    __syncthreads();

    // W2 tile (160x8) + bias (160) into dyn smem past htile
    float* w2s   = (float*)(dyn + EP_W2_OFF);
    float* biass = (float*)(dyn + EP_B1_OFF);
    {
        const float4* src = (const float4*)(W2 + ((size_t)e*H_ + n0)*KK);
        ((float4*)w2s)[tid] = src[tid];
        if(tid < 64) ((float4*)w2s)[256+tid] = src[256+tid];
        if(tid < 40) ((float4*)biass)[tid] = ((const float4*)(b1 + (size_t)e*H_ + n0))[tid];
    }
    __syncthreads();

    // epilogue: bias + ReLU -> htile [128][HTS]
    float* ht = (float*)dyn;
    const int g = lane >> 2, tg2 = (lane & 3)*2;
#pragma unroll
    for(int mi=0; mi<2; mi++){
        int rr = warp_m*32 + mi*16 + g;
#pragma unroll
        for(int ni=0; ni<10; ni++){
            int c0 = warp_n*80 + ni*8 + tg2;
            float2 v0, v1;
            v0.x = fmaxf(acc[mi][ni][0] + biass[c0],   0.f);
            v0.y = fmaxf(acc[mi][ni][1] + biass[c0+1], 0.f);
            v1.x = fmaxf(acc[mi][ni][2] + biass[c0],   0.f);
            v1.y = fmaxf(acc[mi][ni][3] + biass[c0+1], 0.f);
            *(float2*)&ht[(size_t)rr*HTS + c0]     = v0;
            *(float2*)&ht[(size_t)(rr+8)*HTS + c0] = v1;
        }
    }
    __syncthreads();

    // GEMM2 partials: 256 threads -> 128 rows x 2 halves of 80 cols
    {
        const int row = tid >> 1, q = tid & 1;
        const float* hp = &ht[(size_t)row*HTS + q*80];
        const float* wp = &w2s[q*80*8];
        float pl[8];
#pragma unroll
        for(int k=0;k<8;k++) pl[k]=0.f;
#pragma unroll
        for(int cc=0; cc<80; cc++){
            int cr = cc + q; if(cr >= 80) cr -= 80;   // stagger q0/q1 bank phases
            float h = hp[cr];
            const float4* w4 = (const float4*)&wp[cr*8];
            float4 wa = w4[0], wb = w4[1];
            pl[0]=fmaf(h,wa.x,pl[0]); pl[1]=fmaf(h,wa.y,pl[1]);
            pl[2]=fmaf(h,wa.z,pl[2]); pl[3]=fmaf(h,wa.w,pl[3]);
            pl[4]=fmaf(h,wb.x,pl[4]); pl[5]=fmaf(h,wb.y,pl[5]);
            pl[6]=fmaf(h,wb.z,pl[6]); pl[7]=fmaf(h,wb.w,pl[7]);
        }
#pragma unroll
        for(int k=0;k<8;k++) pl[k] += __shfl_xor_sync(0xFFFFFFFFu, pl[k], 1);
        float* dst = gPart + (((size_t)e*NB + blockIdx.y)*B_ + (m0+row))*KK + q*4;
        *(float4*)dst = make_float4(pl[q*4], pl[q*4+1], pl[q*4+2], pl[q*4+3]);
    }
}

// ---- tail: sum 16 partials per (e,k), +b2, softmax, path products
__global__ __launch_bounds__(256) void tail_kernel(const float* __restrict__ b2,
                                                   float* __restrict__ out){
    const int b = blockIdx.x, tid = threadIdx.x;
    __shared__ float part[144][8];
    __shared__ float logits_s[9][8];
    __shared__ float probs_s[9][8];
    for(int t=tid; t<144; t+=256){
        const float4* src = (const float4*)(gPart + ((size_t)t*B_ + b)*KK);
        *(float4*)&part[t][0] = src[0];
        *(float4*)&part[t][4] = src[1];
    }
    __syncthreads();
    if(tid < 72){
        int e = tid>>3, k = tid&7;
        float s = 0.f;
#pragma unroll
        for(int j=0;j<NB;j++) s += part[e*NB+j][k];
        float lv = s + b2[tid];
        logits_s[e][k] = lv;
        out[(size_t)B_*73 + ((size_t)e*B_ + b)*KK + k] = lv;
    }
    __syncthreads();
    if(tid < 9){
        float m = -INFINITY;
#pragma unroll
        for(int k=0;k<8;k++) m = fmaxf(m, logits_s[tid][k]);
        float ex[8], s = 0.f;
#pragma unroll
        for(int k=0;k<8;k++){ ex[k] = expf(logits_s[tid][k]-m); s += ex[k]; }
        float inv = 1.f/s;
#pragma unroll
        for(int k=0;k<8;k++) probs_s[tid][k] = ex[k]*inv;
    }
    __syncthreads();
    if(tid < 73){
        float v;
        if(tid==0) v = 1.f;
        else if(tid<9) v = probs_s[0][tid-1];
        else { int t = tid-9; v = probs_s[0][t>>3]*probs_s[1+(t>>3)][t&7]; }
        out[(size_t)b*73 + tid] = v;
    }
}

extern "C" void kernel_launch(void* const* d_in, const int* in_sizes, int n_in,
                              void* d_out, int out_size){
    const float* x  = (const float*)d_in[0];
    const float* W1 = (const float*)d_in[1];
    const float* b1 = (const float*)d_in[2];
    const float* W2 = (const float*)d_in[3];
    const float* b2 = (const float*)d_in[4];
    float* out = (float*)d_out;

    cudaFuncSetAttribute(gemm_kernel, cudaFuncAttributeMaxDynamicSharedMemorySize, DYN_BYTES);

    conv_x_kernel<<<640, 256>>>(x);
    conv_w1_kernel<<<3600, 256>>>(W1);
    dim3 grid(4, NB, 9);
    gemm_kernel<<<grid, 256, DYN_BYTES>>>(W2, b1);
    tail_kernel<<<B_, 256>>>(b2, out);
}